// round 7
// baseline (speedup 1.0000x reference)
#include <cuda_runtime.h>

#define T_STEPS 20
#define N_NODES 32768
#define D_EMB   64
#define D_H     128
#define D_OUT   5
#define G4      (4*D_H)   // 512

#define MB       128      // nodes per block
#define NT       512      // threads per block (16 warps)
#define SROW     128      // shared row stride (floats) — all hot accesses conflict-free

typedef unsigned long long ull;

// Precomputed embeddings, layout (T, D_EMB, N) so the recurrent kernel reads
// rows exactly like weight/h rows (node-contiguous, 16B aligned).
__device__ float g_emb[(size_t)T_STEPS * D_EMB * N_NODES];

__device__ __forceinline__ ull pk2(float v) {
    ull r; asm("mov.b64 %0, {%1, %1};" : "=l"(r) : "f"(v)); return r;
}
__device__ __forceinline__ ull f2fma(ull a, ull b, ull c) {
    ull d; asm("fma.rn.f32x2 %0, %1, %2, %3;" : "=l"(d) : "l"(a), "l"(b), "l"(c)); return d;
}
__device__ __forceinline__ float2 upk(ull a) {
    float2 f; asm("mov.b64 {%0, %1}, %2;" : "=f"(f.x), "=f"(f.y) : "l"(a)); return f;
}
__device__ __forceinline__ float sigm(float x) {
    return __fdividef(1.f, 1.f + __expf(-x));
}
__device__ __forceinline__ float tanh_(float x) {
    float ax = fabsf(x);
    float e  = __expf(-2.f * ax);
    float r  = __fdividef(1.f - e, 1.f + e);
    return copysignf(r, x);
}

// a = packed pair of 4 node activations; accumulate into 4 gates x 4 channels.
#define GATE_FMA(aXY, Wbase) do {                                              \
    const float* Wr_ = (Wbase);                                                \
    float4 wq_[4];                                                             \
    wq_[0] = *(const float4*)(Wr_);                                            \
    wq_[1] = *(const float4*)(Wr_ + 128);                                      \
    wq_[2] = *(const float4*)(Wr_ + 256);                                      \
    wq_[3] = *(const float4*)(Wr_ + 384);                                      \
    _Pragma("unroll")                                                          \
    for (int g_ = 0; g_ < 4; ++g_) {                                           \
        const float* wf_ = (const float*)&wq_[g_];                             \
        _Pragma("unroll")                                                      \
        for (int ch_ = 0; ch_ < 4; ++ch_) {                                    \
            ull wp_ = pk2(wf_[ch_]);                                           \
            acc[g_][ch_][0] = f2fma((aXY).x, wp_, acc[g_][ch_][0]);            \
            acc[g_][ch_][1] = f2fma((aXY).y, wp_, acc[g_][ch_][1]);            \
        }                                                                      \
    }                                                                          \
} while (0)

// ---------------- Kernel 1: embedding precompute ----------------
__global__ void __launch_bounds__(256) embed_kernel(
    const float* __restrict__ nodes,     // (T, N, 2)
    const float* __restrict__ W_embed,   // (2, 64)
    const float* __restrict__ b_embed)   // (64)
{
    const int n = blockIdx.x * 256 + threadIdx.x;
    const int t = blockIdx.y;
    const float2 x = ((const float2*)nodes)[(size_t)t * N_NODES + n];
    float* dst = g_emb + (size_t)t * D_EMB * N_NODES + n;
    #pragma unroll
    for (int e = 0; e < D_EMB; ++e) {
        float v = fmaf(x.x, __ldg(&W_embed[e]),
                  fmaf(x.y, __ldg(&W_embed[D_EMB + e]), __ldg(&b_embed[e])));
        dst[(size_t)e * N_NODES] = fmaxf(v, 0.f);
    }
}

// ---------------- Kernel 2: recurrent LSTM ----------------
__global__ void __launch_bounds__(NT, 1) vlstm_kernel(
    const int* __restrict__ maskg,            // (T, N) bool -> int32
    const float* __restrict__ h0,             // (N, 128)
    const float* __restrict__ c0,             // (N, 128)
    const float* __restrict__ W_ih,           // (64, 512)
    const float* __restrict__ b_ih,           // (512)
    const float* __restrict__ W_hh,           // (128, 512)
    const float* __restrict__ b_hh,           // (512)
    const float* __restrict__ W_out,          // (128, 5)
    const float* __restrict__ b_out,          // (5)
    float* __restrict__ out)                  // outputs | h_fin | c_fin
{
    extern __shared__ float smem[];
    float* hA      = smem;                         // 128 x 128  [k][node]
    float* hB      = hA + D_H * SROW;              // 128 x 128
    float* cS      = hB + D_H * SROW;              // 128 x 128
    float* mA      = cS + D_H * SROW;              // 128
    float* mB      = mA + MB;                      // 128
    float* bias_sh = mB + MB;                      // 512 (b_ih + b_hh)
    float* wout_sh = bias_sh + G4;                 // 640
    float* bout_sh = wout_sh + D_H * D_OUT;        // 8 (5 used)

    const int tid   = threadIdx.x;
    const int gbase = blockIdx.x * MB;

    // ---- init: h, c transposed into smem; bias/wout caches; mask t=0 ----
    for (int idx = tid; idx < D_H * MB; idx += NT) {
        int node = idx >> 7;
        int k    = idx & 127;
        hA[k * SROW + node] = h0[(size_t)(gbase + node) * D_H + k];
        cS[k * SROW + node] = c0[(size_t)(gbase + node) * D_H + k];
    }
    for (int i = tid; i < G4; i += NT) bias_sh[i] = b_ih[i] + b_hh[i];
    for (int i = tid; i < D_H * D_OUT; i += NT) wout_sh[i] = W_out[i];
    if (tid < D_OUT) bout_sh[tid] = b_out[tid];
    if (tid < MB) mA[tid] = (maskg[gbase + tid] != 0) ? 1.f : 0.f;
    __syncthreads();

    const int warp = tid >> 5;
    const int lane = tid & 31;
    const int n0   = lane * 4;          // 4 nodes per lane

    float* hc = hA;  float* hn = hB;
    float* mc = mA;  float* mn = mB;

    for (int t = 0; t < T_STEPS; ++t) {
        const float* eb = g_emb + (size_t)t * D_EMB * N_NODES + gbase + n0;

        #pragma unroll
        for (int cc = 0; cc < 2; ++cc) {
            const int ch0 = warp * 8 + cc * 4;
            ull acc[4][4][2];
            #pragma unroll
            for (int g = 0; g < 4; ++g)
                #pragma unroll
                for (int ch = 0; ch < 4; ++ch) { acc[g][ch][0] = 0ULL; acc[g][ch][1] = 0ULL; }

            #pragma unroll 2
            for (int k = 0; k < D_EMB; ++k) {
                ulonglong2 a = *(const ulonglong2*)(eb + (size_t)k * N_NODES);
                GATE_FMA(a, W_ih + k * G4 + ch0);
            }
            #pragma unroll 2
            for (int k = 0; k < D_H; ++k) {
                ulonglong2 a = *(const ulonglong2*)&hc[k * SROW + n0];
                GATE_FMA(a, W_hh + k * G4 + ch0);
            }

            const float4 m4 = *(const float4*)&mc[n0];
            const float mm[4] = { m4.x, m4.y, m4.z, m4.w };

            #pragma unroll
            for (int ch = 0; ch < 4; ++ch) {
                const int j  = ch0 + ch;
                const float bi = bias_sh[j];
                const float bf = bias_sh[j + 128];
                const float bg = bias_sh[j + 256];
                const float bo = bias_sh[j + 384];

                float iA[4], fA[4], gA[4], oA[4];
                { float2 p = upk(acc[0][ch][0]); iA[0]=p.x; iA[1]=p.y;
                  float2 q = upk(acc[0][ch][1]); iA[2]=q.x; iA[3]=q.y; }
                { float2 p = upk(acc[1][ch][0]); fA[0]=p.x; fA[1]=p.y;
                  float2 q = upk(acc[1][ch][1]); fA[2]=q.x; fA[3]=q.y; }
                { float2 p = upk(acc[2][ch][0]); gA[0]=p.x; gA[1]=p.y;
                  float2 q = upk(acc[2][ch][1]); gA[2]=q.x; gA[3]=q.y; }
                { float2 p = upk(acc[3][ch][0]); oA[0]=p.x; oA[1]=p.y;
                  float2 q = upk(acc[3][ch][1]); oA[2]=q.x; oA[3]=q.y; }

                const float4 cold4 = *(const float4*)&cS[j * SROW + n0];
                const float4 hold4 = *(const float4*)&hc[j * SROW + n0];
                const float coldA[4] = { cold4.x, cold4.y, cold4.z, cold4.w };
                const float holdA[4] = { hold4.x, hold4.y, hold4.z, hold4.w };

                float cnew[4], hnew[4];
                #pragma unroll
                for (int n = 0; n < 4; ++n) {
                    float ival = sigm(iA[n] + bi);
                    float fval = sigm(fA[n] + bf);
                    float gval = tanh_(gA[n] + bg);
                    float oval = sigm(oA[n] + bo);
                    float cn   = fmaf(fval, coldA[n], ival * gval);
                    float hv   = oval * tanh_(cn);
                    bool  m    = (mm[n] != 0.f);
                    cnew[n] = m ? cn : coldA[n];
                    hnew[n] = m ? hv : holdA[n];
                }
                *(float4*)&cS[j * SROW + n0] = make_float4(cnew[0], cnew[1], cnew[2], cnew[3]);
                *(float4*)&hn[j * SROW + n0] = make_float4(hnew[0], hnew[1], hnew[2], hnew[3]);
            }
        }

        // prefetch next step's mask (same threads that run Stage D -> race-free by program order)
        if (tid < MB && (t + 1) < T_STEPS)
            mn[tid] = (maskg[(size_t)(t + 1) * N_NODES + gbase + tid] != 0) ? 1.f : 0.f;

        __syncthreads();   // hn / cS complete; mn visible for next step

        // ---- Stage D: outputs for step t (reads hn = new h, mc = mask_t) ----
        if (tid < MB) {
            const int node = tid;
            const size_t obase = (size_t)t * N_NODES * D_OUT + (size_t)(gbase + node) * D_OUT;
            if (mc[node] != 0.f) {
                float o0 = bout_sh[0], o1 = bout_sh[1], o2 = bout_sh[2],
                      o3 = bout_sh[3], o4 = bout_sh[4];
                #pragma unroll 4
                for (int k = 0; k < D_H; ++k) {
                    const float hv = hn[k * SROW + node];
                    o0 = fmaf(hv, wout_sh[k * D_OUT + 0], o0);
                    o1 = fmaf(hv, wout_sh[k * D_OUT + 1], o1);
                    o2 = fmaf(hv, wout_sh[k * D_OUT + 2], o2);
                    o3 = fmaf(hv, wout_sh[k * D_OUT + 3], o3);
                    o4 = fmaf(hv, wout_sh[k * D_OUT + 4], o4);
                }
                out[obase + 0] = o0; out[obase + 1] = o1; out[obase + 2] = o2;
                out[obase + 3] = o3; out[obase + 4] = o4;
            } else {
                out[obase + 0] = 0.f; out[obase + 1] = 0.f; out[obase + 2] = 0.f;
                out[obase + 3] = 0.f; out[obase + 4] = 0.f;
            }
        }

        // swap ping-pong buffers
        float* tmp = hc; hc = hn; hn = tmp;
        float* tm  = mc; mc = mn; mn = tm;
    }

    // ---- finals: h_fin, c_fin (final h lives in hc after last swap) ----
    float* hfin = out + (size_t)T_STEPS * N_NODES * D_OUT;
    float* cfin = hfin + (size_t)N_NODES * D_H;
    for (int idx = tid; idx < D_H * MB; idx += NT) {
        int node = idx >> 7;
        int k    = idx & 127;
        hfin[(size_t)(gbase + node) * D_H + k] = hc[k * SROW + node];
        cfin[(size_t)(gbase + node) * D_H + k] = cS[k * SROW + node];
    }
}

extern "C" void kernel_launch(void* const* d_in, const int* in_sizes, int n_in,
                              void* d_out, int out_size)
{
    const float* nodes   = (const float*)d_in[0];
    const int*   mask    = (const int*)d_in[1];      // bool -> int32 in harness
    const float* h0      = (const float*)d_in[2];
    const float* c0      = (const float*)d_in[3];
    const float* W_embed = (const float*)d_in[4];
    const float* b_embed = (const float*)d_in[5];
    const float* W_ih    = (const float*)d_in[6];
    const float* b_ih    = (const float*)d_in[7];
    const float* W_hh    = (const float*)d_in[8];
    const float* b_hh    = (const float*)d_in[9];
    const float* W_out   = (const float*)d_in[10];
    const float* b_out   = (const float*)d_in[11];
    float* out = (float*)d_out;

    // Kernel 1: embeddings
    dim3 eg(N_NODES / 256, T_STEPS);
    embed_kernel<<<eg, 256>>>(nodes, W_embed, b_embed);

    // Kernel 2: recurrence
    const size_t smem = (size_t)(3 * D_H * SROW + 2 * MB + G4 + D_H * D_OUT + 8) * sizeof(float);
    cudaFuncSetAttribute(vlstm_kernel, cudaFuncAttributeMaxDynamicSharedMemorySize, (int)smem);
    vlstm_kernel<<<N_NODES / MB, NT, smem>>>(
        mask, h0, c0, W_ih, b_ih, W_hh, b_hh, W_out, b_out, out);
}

// round 9
// speedup vs baseline: 2.2945x; 2.2945x over previous
#include <cuda_runtime.h>
#include <cuda_bf16.h>
#include <cstdint>

#define T_STEPS 20
#define N_NODES 32768
#define D_H     128
#define D_OUT   5
#define NT      256
#define MB      128

// bf16 matrix strides in BYTES (16B-multiple => ldmatrix-aligned, conflict-free)
#define EMB_STRB 144     // 72 elems
#define H_STRB   272     // 136 elems

// smem byte offsets
#define SO_EMB_HI0 0
#define SO_EMB_LO0 18432
#define SO_EMB_HI1 36864
#define SO_EMB_LO1 55296
#define SO_H_HI0   73728
#define SO_H_LO0   108544
#define SO_H_HI1   143360
#define SO_H_LO1   178176
#define SO_BIAS    212992    // float[512]  [g*128+ch]
#define SO_WOUT    215040    // float[640]
#define SO_BOUT    217600
#define SO_WE      217632    // float[128]
#define SO_BE      218144    // float[64]
#define SO_MSK     218400    // float[128]
#define SO_PART    218912    // float[2][128][5]
#define SMEM_REQ   224032

// B-fragment image: [wsel(2)][colgroup(16)][ks(12)][gate(4)][lane(32)] x 8 bytes
__device__ __align__(16) uint8_t g_Bimg[2 * 16 * 12 * 4 * 32 * 8];

// ---------------- helpers ----------------
static __device__ __forceinline__ uint32_t smem_u32(const void* p){
    uint32_t a; asm("{ .reg .u64 t; cvta.to.shared.u64 t, %1; cvt.u32.u64 %0, t; }" : "=r"(a) : "l"(p));
    return a;
}
static __device__ __forceinline__ void ldsm4(uint32_t* r, uint32_t a){
    asm volatile("ldmatrix.sync.aligned.m8n8.x4.shared.b16 {%0,%1,%2,%3}, [%4];"
        : "=r"(r[0]), "=r"(r[1]), "=r"(r[2]), "=r"(r[3]) : "r"(a));
}
static __device__ __forceinline__ void mma_bf16(float* d, const uint32_t* a, const uint2 b){
    asm volatile("mma.sync.aligned.m16n8k16.row.col.f32.bf16.bf16.f32 "
        "{%0,%1,%2,%3}, {%4,%5,%6,%7}, {%8,%9}, {%0,%1,%2,%3};"
        : "+f"(d[0]), "+f"(d[1]), "+f"(d[2]), "+f"(d[3])
        : "r"(a[0]), "r"(a[1]), "r"(a[2]), "r"(a[3]), "r"(b.x), "r"(b.y));
}
static __device__ __forceinline__ uint16_t bfbits(float v){ return __bfloat16_as_ushort(__float2bfloat16_rn(v)); }
static __device__ __forceinline__ float bflo(uint32_t u){ return __bfloat162float(__ushort_as_bfloat16((uint16_t)(u & 0xffffu))); }
static __device__ __forceinline__ float bfhi(uint32_t u){ return __bfloat162float(__ushort_as_bfloat16((uint16_t)(u >> 16))); }
static __device__ __forceinline__ uint32_t pack_hi2(float a, float b){
    return (uint32_t)bfbits(a) | ((uint32_t)bfbits(b) << 16);
}
static __device__ __forceinline__ uint32_t pack_lo2(float a, float b){
    float ra = a - __bfloat162float(__float2bfloat16_rn(a));
    float rb = b - __bfloat162float(__float2bfloat16_rn(b));
    return (uint32_t)bfbits(ra) | ((uint32_t)bfbits(rb) << 16);
}
static __device__ __forceinline__ float sigm(float x){ return __fdividef(1.f, 1.f + __expf(-x)); }
static __device__ __forceinline__ float tanh_(float x){
    float ax = fabsf(x);
    float e  = __expf(-2.f * ax);
    float r  = __fdividef(1.f - e, 1.f + e);
    return copysignf(r, x);
}

// ---------------- prep: bake B fragment image ----------------
__global__ void prep_kernel(const float* __restrict__ W_ih, const float* __restrict__ W_hh){
    int s = blockIdx.x * 256 + threadIdx.x;          // 49152 frag slots
    int lane = s & 31;
    int g    = (s >> 5) & 3;
    int ks   = (s >> 7) % 12;
    int top  = s / 1536;                             // 0..31
    int wcg  = top & 15;
    int wsel = top >> 4;
    int ch   = wcg * 8 + (lane >> 2);
    int col  = g * 128 + ch;
    uint16_t eb[4];
    #pragma unroll
    for (int e = 0; e < 4; ++e){
        int k16 = (lane & 3) * 2 + (e & 1) + ((e >> 1) * 8);
        int kg  = ks * 16 + k16;
        float w = (kg < 64) ? W_ih[kg * 512 + col] : W_hh[(kg - 64) * 512 + col];
        __nv_bfloat16 hb = __float2bfloat16_rn(w);
        __nv_bfloat16 v  = wsel ? __float2bfloat16_rn(w - __bfloat162float(hb)) : hb;
        eb[e] = __bfloat16_as_ushort(v);
    }
    uint2 o;
    o.x = (uint32_t)eb[0] | ((uint32_t)eb[1] << 16);
    o.y = (uint32_t)eb[2] | ((uint32_t)eb[3] << 16);
    ((uint2*)g_Bimg)[s] = o;
}

// write emb(tt) hi/lo into the given buffers
static __device__ __forceinline__ void emb_write(
    char* sbc, const float* nodes, int gbase, int tid, int tt, int dhi, int dlo)
{
    const int node = tid >> 1, half = tid & 1;
    const float2 x = ((const float2*)nodes)[(size_t)tt * N_NODES + gbase + node];
    const float* we = (const float*)(sbc + SO_WE);
    const float* be = (const float*)(sbc + SO_BE);
    uint32_t hi[16], lo[16];
    #pragma unroll
    for (int i = 0; i < 16; ++i){
        int e0 = half * 32 + 2 * i;
        float v0 = fmaxf(fmaf(x.x, we[e0],     fmaf(x.y, we[64 + e0],     be[e0])),     0.f);
        float v1 = fmaxf(fmaf(x.x, we[e0 + 1], fmaf(x.y, we[64 + e0 + 1], be[e0 + 1])), 0.f);
        hi[i] = pack_hi2(v0, v1);
        lo[i] = pack_lo2(v0, v1);
    }
    char* ph = sbc + dhi + node * EMB_STRB + half * 64;
    char* pl = sbc + dlo + node * EMB_STRB + half * 64;
    #pragma unroll
    for (int q = 0; q < 4; ++q){
        *(uint4*)(ph + q * 16) = make_uint4(hi[q*4+0], hi[q*4+1], hi[q*4+2], hi[q*4+3]);
        *(uint4*)(pl + q * 16) = make_uint4(lo[q*4+0], lo[q*4+1], lo[q*4+2], lo[q*4+3]);
    }
}

// ---------------- main recurrent kernel ----------------
__global__ void __launch_bounds__(NT, 1) vlstm_mma(
    const float* __restrict__ nodes, const int* __restrict__ maskg,
    const float* __restrict__ h0, const float* __restrict__ c0,
    const float* __restrict__ W_embed, const float* __restrict__ b_embed,
    const float* __restrict__ b_ih, const float* __restrict__ b_hh,
    const float* __restrict__ W_out, const float* __restrict__ b_out,
    float* __restrict__ out)
{
    extern __shared__ __align__(16) char sbc[];
    const uint32_t sbase = smem_u32(sbc);
    const int tid = threadIdx.x, warp = tid >> 5, lane = tid & 31;
    const int chBase = warp * 16;
    const int gbase = blockIdx.x * MB;
    const uint2* __restrict__ bimg = (const uint2*)g_Bimg;

    float* biasf = (float*)(sbc + SO_BIAS);
    float* woutf = (float*)(sbc + SO_WOUT);
    float* boutf = (float*)(sbc + SO_BOUT);
    float* mskf  = (float*)(sbc + SO_MSK);
    float* partf = (float*)(sbc + SO_PART);

    for (int i = tid; i < 512; i += NT) biasf[i] = b_ih[i] + b_hh[i];
    for (int i = tid; i < 640; i += NT) woutf[i] = W_out[i];
    if (tid < D_OUT) boutf[tid] = b_out[tid];
    if (tid < 128) ((float*)(sbc + SO_WE))[tid] = W_embed[tid];
    if (tid < 64)  ((float*)(sbc + SO_BE))[tid] = b_embed[tid];
    if (tid < 128) mskf[tid] = (maskg[gbase + tid] != 0) ? 1.f : 0.f;

    // h0 -> H buffers (buf 0)
    {
        __nv_bfloat16* HH = (__nv_bfloat16*)(sbc + SO_H_HI0);
        __nv_bfloat16* HL = (__nv_bfloat16*)(sbc + SO_H_LO0);
        for (int idx = tid; idx < 128 * 128; idx += NT){
            int node = idx >> 7, k = idx & 127;
            float v = h0[(size_t)(gbase + node) * D_H + k];
            __nv_bfloat16 hb = __float2bfloat16_rn(v);
            HH[node * 136 + k] = hb;
            HL[node * 136 + k] = __float2bfloat16_rn(v - __bfloat162float(hb));
        }
    }
    // c state in registers: [ck(2)][rt(4)][rr(2)][nt(2)][cc(2)]
    float c_regs[64];
    #pragma unroll
    for (int ck = 0; ck < 2; ++ck)
      #pragma unroll
      for (int rt = 0; rt < 4; ++rt)
        #pragma unroll
        for (int rr = 0; rr < 2; ++rr)
          #pragma unroll
          for (int nt = 0; nt < 2; ++nt)
            #pragma unroll
            for (int cc = 0; cc < 2; ++cc){
                int row = ck * 64 + rt * 16 + (lane >> 2) + rr * 8;
                int ch  = chBase + nt * 8 + (lane & 3) * 2 + cc;
                c_regs[(((ck * 4 + rt) * 2 + rr) * 2 + nt) * 2 + cc] =
                    c0[(size_t)(gbase + row) * D_H + ch];
            }
    __syncthreads();    // WE/BE ready for emb_write
    emb_write(sbc, nodes, gbase, tid, 0, SO_EMB_HI0, SO_EMB_LO0);
    __syncthreads();

    for (int t = 0; t < T_STEPS; ++t){
        const int p = t & 1;
        const int embHiR = p ? SO_EMB_HI1 : SO_EMB_HI0;
        const int embLoR = p ? SO_EMB_LO1 : SO_EMB_LO0;
        const int hHiR   = p ? SO_H_HI1   : SO_H_HI0;
        const int hLoR   = p ? SO_H_LO1   : SO_H_LO0;
        const int hHiW   = p ? SO_H_HI0   : SO_H_HI1;
        const int hLoW   = p ? SO_H_LO0   : SO_H_LO1;

        // ================= Phase 1: gates + LSTM =================
        #pragma unroll 1
        for (int ck = 0; ck < 2; ++ck){
            const int roff = ck * 64;
            #pragma unroll 1
            for (int nt = 0; nt < 2; ++nt){
                const int wcg = warp * 2 + nt;
                float acc[4][4][4];          // [gate][rowtile][elem]
                #pragma unroll
                for (int g = 0; g < 4; ++g)
                    #pragma unroll
                    for (int rt = 0; rt < 4; ++rt)
                        #pragma unroll
                        for (int e = 0; e < 4; ++e) acc[g][rt][e] = 0.f;

                // chains 1+2: (Ahi + Alo) x Whi
                #pragma unroll 1
                for (int ks = 0; ks < 12; ++ks){
                    uint2 Bf[4];
                    #pragma unroll
                    for (int g = 0; g < 4; ++g)
                        Bf[g] = bimg[((wcg * 12 + ks) * 4 + g) * 32 + lane];
                    uint32_t bHi, bLo, rowTerm;
                    if (ks < 4){
                        rowTerm = (uint32_t)(roff + (lane & 15)) * EMB_STRB + ((lane >> 4) << 4) + ks * 32;
                        bHi = sbase + embHiR + rowTerm;  bLo = sbase + embLoR + rowTerm;
                    } else {
                        rowTerm = (uint32_t)(roff + (lane & 15)) * H_STRB + ((lane >> 4) << 4) + (ks - 4) * 32;
                        bHi = sbase + hHiR + rowTerm;    bLo = sbase + hLoR + rowTerm;
                    }
                    const uint32_t rstep = (ks < 4) ? 16u * EMB_STRB : 16u * H_STRB;
                    #pragma unroll
                    for (int rt = 0; rt < 4; ++rt){
                        uint32_t Af[4];
                        ldsm4(Af, bHi + rt * rstep);
                        #pragma unroll
                        for (int g = 0; g < 4; ++g) mma_bf16(acc[g][rt], Af, Bf[g]);
                        ldsm4(Af, bLo + rt * rstep);
                        #pragma unroll
                        for (int g = 0; g < 4; ++g) mma_bf16(acc[g][rt], Af, Bf[g]);
                    }
                }
                // chain 3: Ahi x Wlo
                #pragma unroll 1
                for (int ks = 0; ks < 12; ++ks){
                    uint2 Bf[4];
                    #pragma unroll
                    for (int g = 0; g < 4; ++g)
                        Bf[g] = bimg[(((16 + wcg) * 12 + ks) * 4 + g) * 32 + lane];
                    uint32_t bHi, rstep;
                    if (ks < 4){
                        bHi = sbase + embHiR + (uint32_t)(roff + (lane & 15)) * EMB_STRB
                            + ((lane >> 4) << 4) + ks * 32;
                        rstep = 16u * EMB_STRB;
                    } else {
                        bHi = sbase + hHiR + (uint32_t)(roff + (lane & 15)) * H_STRB
                            + ((lane >> 4) << 4) + (ks - 4) * 32;
                        rstep = 16u * H_STRB;
                    }
                    #pragma unroll
                    for (int rt = 0; rt < 4; ++rt){
                        uint32_t Af[4];
                        ldsm4(Af, bHi + rt * rstep);
                        #pragma unroll
                        for (int g = 0; g < 4; ++g) mma_bf16(acc[g][rt], Af, Bf[g]);
                    }
                }
                // epilogue for this (ck, nt)
                const int ch0 = chBase + nt * 8 + (lane & 3) * 2;
                #pragma unroll
                for (int rt = 0; rt < 4; ++rt)
                    #pragma unroll
                    for (int rr = 0; rr < 2; ++rr){
                        const int row = roff + rt * 16 + (lane >> 2) + rr * 8;
                        const uint32_t hoff = (uint32_t)row * H_STRB + ch0 * 2;
                        if (mskf[row] != 0.f){
                            float hv[2];
                            #pragma unroll
                            for (int cc = 0; cc < 2; ++cc){
                                const int e  = rr * 2 + cc;
                                const int ch = ch0 + cc;
                                const int ci = (((ck * 4 + rt) * 2 + rr) * 2 + nt) * 2 + cc;
                                float pi = acc[0][rt][e] + biasf[ch];
                                float pf = acc[1][rt][e] + biasf[128 + ch];
                                float pg = acc[2][rt][e] + biasf[256 + ch];
                                float po = acc[3][rt][e] + biasf[384 + ch];
                                float cn = fmaf(sigm(pf), c_regs[ci], sigm(pi) * tanh_(pg));
                                c_regs[ci] = cn;
                                hv[cc] = sigm(po) * tanh_(cn);
                            }
                            *(uint32_t*)(sbc + hHiW + hoff) = pack_hi2(hv[0], hv[1]);
                            *(uint32_t*)(sbc + hLoW + hoff) = pack_lo2(hv[0], hv[1]);
                        } else {
                            *(uint32_t*)(sbc + hHiW + hoff) = *(const uint32_t*)(sbc + hHiR + hoff);
                            *(uint32_t*)(sbc + hLoW + hoff) = *(const uint32_t*)(sbc + hLoR + hoff);
                        }
                    }
            }
        }
        __syncthreads();   // S1: h_{t+1} buffers complete

        // ================= Phase 2a: Stage-D partials =================
        {
            const int node = tid & 127, half = tid >> 7;
            const char* HH = sbc + hHiW + node * H_STRB + half * 128;
            const char* HL = sbc + hLoW + node * H_STRB + half * 128;
            float p0 = 0.f, p1 = 0.f, p2 = 0.f, p3 = 0.f, p4 = 0.f;
            #pragma unroll 4
            for (int k2 = 0; k2 < 32; ++k2){
                uint32_t hh = *(const uint32_t*)(HH + k2 * 4);
                uint32_t ll = *(const uint32_t*)(HL + k2 * 4);
                float h0v = bflo(hh) + bflo(ll);
                float h1v = bfhi(hh) + bfhi(ll);
                const float* w0 = woutf + (half * 64 + 2 * k2) * 5;
                p0 = fmaf(h0v, w0[0], fmaf(h1v, w0[5], p0));
                p1 = fmaf(h0v, w0[1], fmaf(h1v, w0[6], p1));
                p2 = fmaf(h0v, w0[2], fmaf(h1v, w0[7], p2));
                p3 = fmaf(h0v, w0[3], fmaf(h1v, w0[8], p3));
                p4 = fmaf(h0v, w0[4], fmaf(h1v, w0[9], p4));
            }
            float* pp = partf + (half * 128 + node) * 5;
            pp[0] = p0; pp[1] = p1; pp[2] = p2; pp[3] = p3; pp[4] = p4;
        }
        __syncthreads();   // S2: partials visible

        // ================= Phase 2b: reduce + out; next emb/mask =================
        if (tid < 128){
            const size_t obase = (size_t)t * N_NODES * D_OUT + (size_t)(gbase + tid) * D_OUT;
            if (mskf[tid] != 0.f){
                #pragma unroll
                for (int d = 0; d < D_OUT; ++d)
                    out[obase + d] = boutf[d] + partf[tid * 5 + d] + partf[(128 + tid) * 5 + d];
            } else {
                #pragma unroll
                for (int d = 0; d < D_OUT; ++d) out[obase + d] = 0.f;
            }
            if (t + 1 < T_STEPS)
                mskf[tid] = (maskg[(size_t)(t + 1) * N_NODES + gbase + tid] != 0) ? 1.f : 0.f;
        }
        if (t + 1 < T_STEPS)
            emb_write(sbc, nodes, gbase, tid, t + 1,
                      p ? SO_EMB_HI0 : SO_EMB_HI1, p ? SO_EMB_LO0 : SO_EMB_LO1);
        __syncthreads();   // S3: emb/mask ready for next step
    }

    // ---- finals: h from H buf0 (T even), c from registers ----
    float* hfin = out + (size_t)T_STEPS * N_NODES * D_OUT;
    float* cfin = hfin + (size_t)N_NODES * D_H;
    {
        const __nv_bfloat16* HH = (const __nv_bfloat16*)(sbc + SO_H_HI0);
        const __nv_bfloat16* HL = (const __nv_bfloat16*)(sbc + SO_H_LO0);
        for (int idx = tid; idx < 128 * 128; idx += NT){
            int node = idx >> 7, k = idx & 127;
            hfin[(size_t)(gbase + node) * D_H + k] =
                __bfloat162float(HH[node * 136 + k]) + __bfloat162float(HL[node * 136 + k]);
        }
    }
    #pragma unroll
    for (int ck = 0; ck < 2; ++ck)
      #pragma unroll
      for (int rt = 0; rt < 4; ++rt)
        #pragma unroll
        for (int rr = 0; rr < 2; ++rr)
          #pragma unroll
          for (int nt = 0; nt < 2; ++nt)
            #pragma unroll
            for (int cc = 0; cc < 2; ++cc){
                int row = ck * 64 + rt * 16 + (lane >> 2) + rr * 8;
                int ch  = chBase + nt * 8 + (lane & 3) * 2 + cc;
                cfin[(size_t)(gbase + row) * D_H + ch] =
                    c_regs[(((ck * 4 + rt) * 2 + rr) * 2 + nt) * 2 + cc];
            }
}

extern "C" void kernel_launch(void* const* d_in, const int* in_sizes, int n_in,
                              void* d_out, int out_size)
{
    const float* nodes   = (const float*)d_in[0];
    const int*   mask    = (const int*)d_in[1];
    const float* h0      = (const float*)d_in[2];
    const float* c0      = (const float*)d_in[3];
    const float* W_embed = (const float*)d_in[4];
    const float* b_embed = (const float*)d_in[5];
    const float* W_ih    = (const float*)d_in[6];
    const float* b_ih    = (const float*)d_in[7];
    const float* W_hh    = (const float*)d_in[8];
    const float* b_hh    = (const float*)d_in[9];
    const float* W_out   = (const float*)d_in[10];
    const float* b_out   = (const float*)d_in[11];
    float* out = (float*)d_out;

    prep_kernel<<<192, 256>>>(W_ih, W_hh);

    cudaFuncSetAttribute(vlstm_mma, cudaFuncAttributeMaxDynamicSharedMemorySize, SMEM_REQ);
    vlstm_mma<<<N_NODES / MB, NT, SMEM_REQ>>>(
        nodes, mask, h0, c0, W_embed, b_embed, b_ih, b_hh, W_out, b_out, out);
}

// round 10
// speedup vs baseline: 3.2313x; 1.4082x over previous
#include <cuda_runtime.h>
#include <cuda_bf16.h>
#include <cstdint>

#define T_STEPS 20
#define N_NODES 32768
#define D_H     128
#define D_OUT   5
#define NT      512
#define MB      128

// bf16 matrix strides in BYTES (16B-multiple => ldmatrix-aligned, conflict-free)
#define EMB_STRB 144     // 72 elems
#define H_STRB   272     // 136 elems

// smem byte offsets
#define SO_EMB_HI0 0
#define SO_EMB_LO0 18432
#define SO_EMB_HI1 36864
#define SO_EMB_LO1 55296
#define SO_H_HI0   73728
#define SO_H_LO0   108544
#define SO_H_HI1   143360
#define SO_H_LO1   178176
#define SO_BIAS    212992    // float[512]  [g*128+ch]
#define SO_WOUT    215040    // float[640]
#define SO_BOUT    217600
#define SO_WE      217632    // float[128]
#define SO_BE      218144    // float[64]
#define SO_MSK     218400    // float[128]
#define SO_PART    218912    // float[4][128][5] = 10240 B
#define SMEM_REQ   229152

// B-fragment image: [wsel(2)][colgroup(16)][ks(12)][gate(4)][lane(32)] x 8 bytes
__device__ __align__(16) uint8_t g_Bimg[2 * 16 * 12 * 4 * 32 * 8];

// ---------------- helpers ----------------
static __device__ __forceinline__ uint32_t smem_u32(const void* p){
    uint32_t a; asm("{ .reg .u64 t; cvta.to.shared.u64 t, %1; cvt.u32.u64 %0, t; }" : "=r"(a) : "l"(p));
    return a;
}
static __device__ __forceinline__ void ldsm4(uint32_t* r, uint32_t a){
    asm volatile("ldmatrix.sync.aligned.m8n8.x4.shared.b16 {%0,%1,%2,%3}, [%4];"
        : "=r"(r[0]), "=r"(r[1]), "=r"(r[2]), "=r"(r[3]) : "r"(a));
}
static __device__ __forceinline__ void mma_bf16(float* d, const uint32_t* a, const uint2 b){
    asm volatile("mma.sync.aligned.m16n8k16.row.col.f32.bf16.bf16.f32 "
        "{%0,%1,%2,%3}, {%4,%5,%6,%7}, {%8,%9}, {%0,%1,%2,%3};"
        : "+f"(d[0]), "+f"(d[1]), "+f"(d[2]), "+f"(d[3])
        : "r"(a[0]), "r"(a[1]), "r"(a[2]), "r"(a[3]), "r"(b.x), "r"(b.y));
}
static __device__ __forceinline__ uint16_t bfbits(float v){ return __bfloat16_as_ushort(__float2bfloat16_rn(v)); }
static __device__ __forceinline__ float bflo(uint32_t u){ return __bfloat162float(__ushort_as_bfloat16((uint16_t)(u & 0xffffu))); }
static __device__ __forceinline__ float bfhi(uint32_t u){ return __bfloat162float(__ushort_as_bfloat16((uint16_t)(u >> 16))); }
static __device__ __forceinline__ uint32_t pack_hi2(float a, float b){
    return (uint32_t)bfbits(a) | ((uint32_t)bfbits(b) << 16);
}
static __device__ __forceinline__ uint32_t pack_lo2(float a, float b){
    float ra = a - __bfloat162float(__float2bfloat16_rn(a));
    float rb = b - __bfloat162float(__float2bfloat16_rn(b));
    return (uint32_t)bfbits(ra) | ((uint32_t)bfbits(rb) << 16);
}
static __device__ __forceinline__ float sigm(float x){ return __fdividef(1.f, 1.f + __expf(-x)); }
static __device__ __forceinline__ float tanh_(float x){
    float ax = fabsf(x);
    float e  = __expf(-2.f * ax);
    float r  = __fdividef(1.f - e, 1.f + e);
    return copysignf(r, x);
}

// ---------------- prep: bake B fragment image ----------------
__global__ void prep_kernel(const float* __restrict__ W_ih, const float* __restrict__ W_hh){
    int s = blockIdx.x * 256 + threadIdx.x;          // 49152 frag slots
    int lane = s & 31;
    int g    = (s >> 5) & 3;
    int ks   = (s >> 7) % 12;
    int top  = s / 1536;                             // 0..31
    int wcg  = top & 15;
    int wsel = top >> 4;
    int ch   = wcg * 8 + (lane >> 2);
    int col  = g * 128 + ch;
    uint16_t eb[4];
    #pragma unroll
    for (int e = 0; e < 4; ++e){
        int k16 = (lane & 3) * 2 + (e & 1) + ((e >> 1) * 8);
        int kg  = ks * 16 + k16;
        float w = (kg < 64) ? W_ih[kg * 512 + col] : W_hh[(kg - 64) * 512 + col];
        __nv_bfloat16 hb = __float2bfloat16_rn(w);
        __nv_bfloat16 v  = wsel ? __float2bfloat16_rn(w - __bfloat162float(hb)) : hb;
        eb[e] = __bfloat16_as_ushort(v);
    }
    uint2 o;
    o.x = (uint32_t)eb[0] | ((uint32_t)eb[1] << 16);
    o.y = (uint32_t)eb[2] | ((uint32_t)eb[3] << 16);
    ((uint2*)g_Bimg)[s] = o;
}

// write emb(tt) hi/lo into the given buffers (512 threads: node = tid>>2, quarter = tid&3)
static __device__ __forceinline__ void emb_write(
    char* sbc, const float* nodes, int gbase, int tid, int tt, int dhi, int dlo)
{
    const int node = tid >> 2, qq = tid & 3;
    const float2 x = ((const float2*)nodes)[(size_t)tt * N_NODES + gbase + node];
    const float* we = (const float*)(sbc + SO_WE);
    const float* be = (const float*)(sbc + SO_BE);
    uint32_t hi[8], lo[8];
    #pragma unroll
    for (int i = 0; i < 8; ++i){
        int e0 = qq * 16 + 2 * i;
        float v0 = fmaxf(fmaf(x.x, we[e0],     fmaf(x.y, we[64 + e0],     be[e0])),     0.f);
        float v1 = fmaxf(fmaf(x.x, we[e0 + 1], fmaf(x.y, we[64 + e0 + 1], be[e0 + 1])), 0.f);
        hi[i] = pack_hi2(v0, v1);
        lo[i] = pack_lo2(v0, v1);
    }
    char* ph = sbc + dhi + node * EMB_STRB + qq * 32;
    char* pl = sbc + dlo + node * EMB_STRB + qq * 32;
    *(uint4*)(ph)      = make_uint4(hi[0], hi[1], hi[2], hi[3]);
    *(uint4*)(ph + 16) = make_uint4(hi[4], hi[5], hi[6], hi[7]);
    *(uint4*)(pl)      = make_uint4(lo[0], lo[1], lo[2], lo[3]);
    *(uint4*)(pl + 16) = make_uint4(lo[4], lo[5], lo[6], lo[7]);
}

// ---------------- main recurrent kernel ----------------
__global__ void __launch_bounds__(NT, 1) vlstm_mma(
    const float* __restrict__ nodes, const int* __restrict__ maskg,
    const float* __restrict__ h0, const float* __restrict__ c0,
    const float* __restrict__ W_embed, const float* __restrict__ b_embed,
    const float* __restrict__ b_ih, const float* __restrict__ b_hh,
    const float* __restrict__ W_out, const float* __restrict__ b_out,
    float* __restrict__ out)
{
    extern __shared__ __align__(16) char sbc[];
    const uint32_t sbase = smem_u32(sbc);
    const int tid = threadIdx.x, warp = tid >> 5, lane = tid & 31;
    const int chBase = warp * 8;                 // 16 warps x 8 channels
    const int gbase = blockIdx.x * MB;
    const uint2* __restrict__ bimg = (const uint2*)g_Bimg;

    float* biasf = (float*)(sbc + SO_BIAS);
    float* woutf = (float*)(sbc + SO_WOUT);
    float* boutf = (float*)(sbc + SO_BOUT);
    float* mskf  = (float*)(sbc + SO_MSK);
    float* partf = (float*)(sbc + SO_PART);

    for (int i = tid; i < 512; i += NT) biasf[i] = b_ih[i] + b_hh[i];
    for (int i = tid; i < 640; i += NT) woutf[i] = W_out[i];
    if (tid < D_OUT) boutf[tid] = b_out[tid];
    if (tid < 128) ((float*)(sbc + SO_WE))[tid] = W_embed[tid];
    if (tid < 64)  ((float*)(sbc + SO_BE))[tid] = b_embed[tid];
    if (tid < 128) mskf[tid] = (maskg[gbase + tid] != 0) ? 1.f : 0.f;

    // h0 -> H buffers (buf 0)
    {
        __nv_bfloat16* HH = (__nv_bfloat16*)(sbc + SO_H_HI0);
        __nv_bfloat16* HL = (__nv_bfloat16*)(sbc + SO_H_LO0);
        for (int idx = tid; idx < 128 * 128; idx += NT){
            int node = idx >> 7, k = idx & 127;
            float v = h0[(size_t)(gbase + node) * D_H + k];
            __nv_bfloat16 hb = __float2bfloat16_rn(v);
            HH[node * 136 + k] = hb;
            HL[node * 136 + k] = __float2bfloat16_rn(v - __bfloat162float(hb));
        }
    }
    // c state in registers: [ck(2)][rt(4)][rr(2)][cc(2)] = 32
    float c_regs[32];
    #pragma unroll
    for (int ck = 0; ck < 2; ++ck)
      #pragma unroll
      for (int rt = 0; rt < 4; ++rt)
        #pragma unroll
        for (int rr = 0; rr < 2; ++rr)
          #pragma unroll
          for (int cc = 0; cc < 2; ++cc){
              int row = ck * 64 + rt * 16 + (lane >> 2) + rr * 8;
              int ch  = chBase + (lane & 3) * 2 + cc;
              c_regs[((ck * 4 + rt) * 2 + rr) * 2 + cc] =
                  c0[(size_t)(gbase + row) * D_H + ch];
          }
    __syncthreads();    // WE/BE ready for emb_write
    emb_write(sbc, nodes, gbase, tid, 0, SO_EMB_HI0, SO_EMB_LO0);
    __syncthreads();

    for (int t = 0; t < T_STEPS; ++t){
        const int p = t & 1;
        const int embHiR = p ? SO_EMB_HI1 : SO_EMB_HI0;
        const int embLoR = p ? SO_EMB_LO1 : SO_EMB_LO0;
        const int hHiR   = p ? SO_H_HI1   : SO_H_HI0;
        const int hLoR   = p ? SO_H_LO1   : SO_H_LO0;
        const int hHiW   = p ? SO_H_HI0   : SO_H_HI1;
        const int hLoW   = p ? SO_H_LO0   : SO_H_LO1;

        // ================= Phase 1: gates + LSTM =================
        #pragma unroll 1
        for (int ck = 0; ck < 2; ++ck){
            const int roff = ck * 64;
            float acc[4][4][4];          // [gate][rowtile][elem]
            #pragma unroll
            for (int g = 0; g < 4; ++g)
                #pragma unroll
                for (int rt = 0; rt < 4; ++rt)
                    #pragma unroll
                    for (int e = 0; e < 4; ++e) acc[g][rt][e] = 0.f;

            // fused chains: Ahi x (Whi, Wlo) + Alo x Whi
            #pragma unroll 1
            for (int ks = 0; ks < 12; ++ks){
                uint2 BfH[4], BfL[4];
                #pragma unroll
                for (int g = 0; g < 4; ++g){
                    BfH[g] = bimg[((warp * 12 + ks) * 4 + g) * 32 + lane];
                    BfL[g] = bimg[(((16 + warp) * 12 + ks) * 4 + g) * 32 + lane];
                }
                uint32_t bHi, bLo, rstep;
                if (ks < 4){
                    uint32_t rowTerm = (uint32_t)(roff + (lane & 15)) * EMB_STRB
                                     + ((lane >> 4) << 4) + ks * 32;
                    bHi = sbase + embHiR + rowTerm;  bLo = sbase + embLoR + rowTerm;
                    rstep = 16u * EMB_STRB;
                } else {
                    uint32_t rowTerm = (uint32_t)(roff + (lane & 15)) * H_STRB
                                     + ((lane >> 4) << 4) + (ks - 4) * 32;
                    bHi = sbase + hHiR + rowTerm;    bLo = sbase + hLoR + rowTerm;
                    rstep = 16u * H_STRB;
                }
                #pragma unroll
                for (int rt = 0; rt < 4; ++rt){
                    uint32_t Af[4];
                    ldsm4(Af, bHi + rt * rstep);
                    #pragma unroll
                    for (int g = 0; g < 4; ++g) mma_bf16(acc[g][rt], Af, BfH[g]);
                    #pragma unroll
                    for (int g = 0; g < 4; ++g) mma_bf16(acc[g][rt], Af, BfL[g]);
                    ldsm4(Af, bLo + rt * rstep);
                    #pragma unroll
                    for (int g = 0; g < 4; ++g) mma_bf16(acc[g][rt], Af, BfH[g]);
                }
            }
            // epilogue for this ck
            const int ch0 = chBase + (lane & 3) * 2;
            #pragma unroll
            for (int rt = 0; rt < 4; ++rt)
                #pragma unroll
                for (int rr = 0; rr < 2; ++rr){
                    const int row = roff + rt * 16 + (lane >> 2) + rr * 8;
                    const uint32_t hoff = (uint32_t)row * H_STRB + ch0 * 2;
                    if (mskf[row] != 0.f){
                        float hv[2];
                        #pragma unroll
                        for (int cc = 0; cc < 2; ++cc){
                            const int e  = rr * 2 + cc;
                            const int ch = ch0 + cc;
                            const int ci = ((ck * 4 + rt) * 2 + rr) * 2 + cc;
                            float pi = acc[0][rt][e] + biasf[ch];
                            float pf = acc[1][rt][e] + biasf[128 + ch];
                            float pg = acc[2][rt][e] + biasf[256 + ch];
                            float po = acc[3][rt][e] + biasf[384 + ch];
                            float cn = fmaf(sigm(pf), c_regs[ci], sigm(pi) * tanh_(pg));
                            c_regs[ci] = cn;
                            hv[cc] = sigm(po) * tanh_(cn);
                        }
                        *(uint32_t*)(sbc + hHiW + hoff) = pack_hi2(hv[0], hv[1]);
                        *(uint32_t*)(sbc + hLoW + hoff) = pack_lo2(hv[0], hv[1]);
                    } else {
                        *(uint32_t*)(sbc + hHiW + hoff) = *(const uint32_t*)(sbc + hHiR + hoff);
                        *(uint32_t*)(sbc + hLoW + hoff) = *(const uint32_t*)(sbc + hLoR + hoff);
                    }
                }
        }
        __syncthreads();   // S1: h_{t+1} buffers complete

        // ================= Phase 2a: Stage-D partials (4-way k-split) =================
        {
            const int node = tid & 127, q = tid >> 7;      // q in 0..3, 32 features each
            const char* HH = sbc + hHiW + node * H_STRB + q * 64;
            const char* HL = sbc + hLoW + node * H_STRB + q * 64;
            float p0 = 0.f, p1 = 0.f, p2 = 0.f, p3 = 0.f, p4 = 0.f;
            #pragma unroll 4
            for (int k2 = 0; k2 < 16; ++k2){
                uint32_t hh = *(const uint32_t*)(HH + k2 * 4);
                uint32_t ll = *(const uint32_t*)(HL + k2 * 4);
                float h0v = bflo(hh) + bflo(ll);
                float h1v = bfhi(hh) + bfhi(ll);
                const float* w0 = woutf + (q * 32 + 2 * k2) * 5;
                p0 = fmaf(h0v, w0[0], fmaf(h1v, w0[5], p0));
                p1 = fmaf(h0v, w0[1], fmaf(h1v, w0[6], p1));
                p2 = fmaf(h0v, w0[2], fmaf(h1v, w0[7], p2));
                p3 = fmaf(h0v, w0[3], fmaf(h1v, w0[8], p3));
                p4 = fmaf(h0v, w0[4], fmaf(h1v, w0[9], p4));
            }
            float* pp = partf + (q * 128 + node) * 5;
            pp[0] = p0; pp[1] = p1; pp[2] = p2; pp[3] = p3; pp[4] = p4;
        }
        __syncthreads();   // S2: partials visible

        // ================= Phase 2b: reduce + out; next emb/mask =================
        if (tid < 128){
            const size_t obase = (size_t)t * N_NODES * D_OUT + (size_t)(gbase + tid) * D_OUT;
            if (mskf[tid] != 0.f){
                #pragma unroll
                for (int d = 0; d < D_OUT; ++d)
                    out[obase + d] = boutf[d]
                        + partf[tid * 5 + d]         + partf[(128 + tid) * 5 + d]
                        + partf[(256 + tid) * 5 + d] + partf[(384 + tid) * 5 + d];
            } else {
                #pragma unroll
                for (int d = 0; d < D_OUT; ++d) out[obase + d] = 0.f;
            }
            if (t + 1 < T_STEPS)
                mskf[tid] = (maskg[(size_t)(t + 1) * N_NODES + gbase + tid] != 0) ? 1.f : 0.f;
        }
        if (t + 1 < T_STEPS)
            emb_write(sbc, nodes, gbase, tid, t + 1,
                      p ? SO_EMB_HI0 : SO_EMB_HI1, p ? SO_EMB_LO0 : SO_EMB_LO1);
        __syncthreads();   // S3: emb/mask ready for next step
    }

    // ---- finals: h from H buf0 (T even), c from registers ----
    float* hfin = out + (size_t)T_STEPS * N_NODES * D_OUT;
    float* cfin = hfin + (size_t)N_NODES * D_H;
    {
        const __nv_bfloat16* HH = (const __nv_bfloat16*)(sbc + SO_H_HI0);
        const __nv_bfloat16* HL = (const __nv_bfloat16*)(sbc + SO_H_LO0);
        for (int idx = tid; idx < 128 * 128; idx += NT){
            int node = idx >> 7, k = idx & 127;
            hfin[(size_t)(gbase + node) * D_H + k] =
                __bfloat162float(HH[node * 136 + k]) + __bfloat162float(HL[node * 136 + k]);
        }
    }
    #pragma unroll
    for (int ck = 0; ck < 2; ++ck)
      #pragma unroll
      for (int rt = 0; rt < 4; ++rt)
        #pragma unroll
        for (int rr = 0; rr < 2; ++rr)
          #pragma unroll
          for (int cc = 0; cc < 2; ++cc){
              int row = ck * 64 + rt * 16 + (lane >> 2) + rr * 8;
              int ch  = chBase + (lane & 3) * 2 + cc;
              cfin[(size_t)(gbase + row) * D_H + ch] =
                  c_regs[((ck * 4 + rt) * 2 + rr) * 2 + cc];
          }
}

extern "C" void kernel_launch(void* const* d_in, const int* in_sizes, int n_in,
                              void* d_out, int out_size)
{
    const float* nodes   = (const float*)d_in[0];
    const int*   mask    = (const int*)d_in[1];
    const float* h0      = (const float*)d_in[2];
    const float* c0      = (const float*)d_in[3];
    const float* W_embed = (const float*)d_in[4];
    const float* b_embed = (const float*)d_in[5];
    const float* W_ih    = (const float*)d_in[6];
    const float* b_ih    = (const float*)d_in[7];
    const float* W_hh    = (const float*)d_in[8];
    const float* b_hh    = (const float*)d_in[9];
    const float* W_out   = (const float*)d_in[10];
    const float* b_out   = (const float*)d_in[11];
    float* out = (float*)d_out;

    prep_kernel<<<192, 256>>>(W_ih, W_hh);

    cudaFuncSetAttribute(vlstm_mma, cudaFuncAttributeMaxDynamicSharedMemorySize, SMEM_REQ);
    vlstm_mma<<<N_NODES / MB, NT, SMEM_REQ>>>(
        nodes, mask, h0, c0, W_embed, b_embed, b_ih, b_hh, W_out, b_out, out);
}